// round 1
// baseline (speedup 1.0000x reference)
#include <cuda_runtime.h>
#include <math.h>

#define Bq   2
#define Lq   4096
#define Dq   512
#define Hq   8
#define DKq  64
#define BHq  (Bq*Hq)
#define Mrows (Bq*Lq)          // 8192

// ---------------- scratch (device globals; no allocations allowed) ----------
__device__ float g_Q[BHq * Lq * DKq];     // [b*H+h][l][dk]
__device__ float g_K[BHq * Lq * DKq];
__device__ float g_V[BHq * Lq * DKq];
__device__ float g_ctx[Mrows * Dq];       // [b*L + l][D]

// ---------------- generic 64x64x16 tiled fp32 GEMM: out = x @ W + bias ------
// mode 0/1/2 : write head-split into g_Q/g_K/g_V
// mode 3     : x := g_ctx, write plain into out_plain
__global__ void gemm64(const float* __restrict__ x,
                       const float* __restrict__ W,
                       const float* __restrict__ bias,
                       float* __restrict__ out_plain,
                       int mode)
{
    __shared__ float As[16][64];
    __shared__ float Bs[16][64];

    const float* xx = (mode == 3) ? g_ctx : x;
    float* out_hs = (mode == 0) ? g_Q : (mode == 1) ? g_K : g_V;

    const int m0 = blockIdx.y * 64;
    const int n0 = blockIdx.x * 64;
    const int tid = threadIdx.x;          // 0..255
    const int tr = tid >> 4;              // 0..15
    const int tc = tid & 15;              // 0..15

    float acc[4][4];
    #pragma unroll
    for (int i = 0; i < 4; i++)
        #pragma unroll
        for (int j = 0; j < 4; j++) acc[i][j] = 0.f;

    for (int k0 = 0; k0 < Dq; k0 += 16) {
        // load A tile 64x16 (transposed into As[k][m])
        {
            int r = tid >> 2;               // 0..63
            int c = (tid & 3) << 2;         // 0,4,8,12
            float4 a = *(const float4*)&xx[(size_t)(m0 + r) * Dq + k0 + c];
            As[c + 0][r] = a.x; As[c + 1][r] = a.y;
            As[c + 2][r] = a.z; As[c + 3][r] = a.w;
        }
        // load B tile 16x64
        {
            int r = tid >> 4;               // 0..15
            int c = (tid & 15) << 2;        // 0..60
            *(float4*)&Bs[r][c] = *(const float4*)&W[(size_t)(k0 + r) * Dq + n0 + c];
        }
        __syncthreads();

        #pragma unroll
        for (int kk = 0; kk < 16; kk++) {
            float4 a4 = *(const float4*)&As[kk][tr << 2];
            float4 b4 = *(const float4*)&Bs[kk][tc << 2];
            float av[4] = {a4.x, a4.y, a4.z, a4.w};
            float bv[4] = {b4.x, b4.y, b4.z, b4.w};
            #pragma unroll
            for (int i = 0; i < 4; i++)
                #pragma unroll
                for (int j = 0; j < 4; j++)
                    acc[i][j] += av[i] * bv[j];
        }
        __syncthreads();
    }

    // epilogue
    #pragma unroll
    for (int i = 0; i < 4; i++) {
        int m = m0 + (tr << 2) + i;
        #pragma unroll
        for (int j = 0; j < 4; j++) {
            int n = n0 + (tc << 2) + j;
            float val = acc[i][j] + bias[n];
            if (mode < 3) {
                int b = m >> 12;            // m / 4096
                int l = m & 4095;
                int h = n >> 6;
                int dk = n & 63;
                out_hs[(((size_t)(b * Hq + h) * Lq + l) << 6) + dk] = val;
            } else {
                out_plain[(size_t)m * Dq + n] = val;
            }
        }
    }
}

// ---------------- causal flash attention, fp32 ------------------------------
// grid: (L/64, B*H), block: 64 threads, one query row per thread
__global__ void attn64(void)
{
    const int bh  = blockIdx.y;                 // 0..15
    const int qt  = blockIdx.x;                 // 0..63
    const int tid = threadIdx.x;                // 0..63
    const int qi  = qt * 64 + tid;

    const float* Qb = g_Q + (size_t)bh * Lq * DKq;
    const float* Kb = g_K + (size_t)bh * Lq * DKq;
    const float* Vb = g_V + (size_t)bh * Lq * DKq;

    __shared__ float Ks[64][64];
    __shared__ float Vs[64][64];
    __shared__ float Ss[64][65];                // padded: no bank conflicts

    float qreg[64];
    #pragma unroll
    for (int d = 0; d < 64; d += 4) {
        float4 t = *(const float4*)&Qb[((size_t)qi << 6) + d];
        qreg[d + 0] = t.x * 0.125f;             // scale = 1/sqrt(64)
        qreg[d + 1] = t.y * 0.125f;
        qreg[d + 2] = t.z * 0.125f;
        qreg[d + 3] = t.w * 0.125f;
    }

    float acc[64];
    #pragma unroll
    for (int d = 0; d < 64; d++) acc[d] = 0.f;
    float mrun = -INFINITY, lrun = 0.f;

    for (int kt = 0; kt <= qt; kt++) {
        const int k0 = kt * 64;

        // cooperative, coalesced K/V tile load (64x64 floats each)
        for (int i = tid; i < 64 * 16; i += 64) {
            int r = i >> 4;
            int c = (i & 15) << 2;
            *(float4*)&Ks[r][c] = *(const float4*)&Kb[((size_t)(k0 + r) << 6) + c];
            *(float4*)&Vs[r][c] = *(const float4*)&Vb[((size_t)(k0 + r) << 6) + c];
        }
        __syncthreads();

        const bool full = (k0 + 63 <= qi);

        // pass 1: scores + tile max
        float tmax = -INFINITY;
        for (int j = 0; j < 64; j++) {
            float s;
            if (full || (k0 + j <= qi)) {
                s = 0.f;
                #pragma unroll
                for (int d = 0; d < 64; d += 4) {
                    float4 kk = *(const float4*)&Ks[j][d];
                    s += qreg[d + 0] * kk.x;
                    s += qreg[d + 1] * kk.y;
                    s += qreg[d + 2] * kk.z;
                    s += qreg[d + 3] * kk.w;
                }
            } else {
                s = -INFINITY;
            }
            Ss[tid][j] = s;
            tmax = fmaxf(tmax, s);
        }

        // pass 2: online-softmax update
        float mnew = fmaxf(mrun, tmax);
        float corr = __expf(mrun - mnew);       // 0 on first tile
        float lsum = 0.f;
        #pragma unroll 4
        for (int j = 0; j < 64; j++) {
            float p = __expf(Ss[tid][j] - mnew);
            Ss[tid][j] = p;
            lsum += p;
        }
        lrun = lrun * corr + lsum;
        #pragma unroll
        for (int d = 0; d < 64; d++) acc[d] *= corr;

        // pass 3: P @ V
        for (int j = 0; j < 64; j++) {
            float p = Ss[tid][j];
            #pragma unroll
            for (int d = 0; d < 64; d += 4) {
                float4 vv = *(const float4*)&Vs[j][d];
                acc[d + 0] += p * vv.x;
                acc[d + 1] += p * vv.y;
                acc[d + 2] += p * vv.z;
                acc[d + 3] += p * vv.w;
            }
        }
        mrun = mnew;
        __syncthreads();
    }

    // epilogue: normalize, write to ctx [b*L + l][h*64 + d]
    const float inv = 1.f / lrun;
    const int b = bh >> 3;
    const int h = bh & 7;
    float* outp = g_ctx + ((size_t)(b * Lq + qi) * Dq) + h * 64;
    #pragma unroll
    for (int d = 0; d < 64; d += 4) {
        float4 t;
        t.x = acc[d + 0] * inv;
        t.y = acc[d + 1] * inv;
        t.z = acc[d + 2] * inv;
        t.w = acc[d + 3] * inv;
        *(float4*)&outp[d] = t;
    }
}

// ---------------- launch ----------------------------------------------------
extern "C" void kernel_launch(void* const* d_in, const int* in_sizes, int n_in,
                              void* d_out, int out_size)
{
    const float* q  = (const float*)d_in[0];
    const float* k  = (const float*)d_in[1];
    const float* v  = (const float*)d_in[2];
    // d_in[3] = mask (int32 tril) — causality handled analytically
    const float* Wq = (const float*)d_in[4];
    const float* bq = (const float*)d_in[5];
    const float* Wk = (const float*)d_in[6];
    const float* bk = (const float*)d_in[7];
    const float* Wv = (const float*)d_in[8];
    const float* bv = (const float*)d_in[9];
    const float* Wo = (const float*)d_in[10];
    const float* bo = (const float*)d_in[11];
    float* out = (float*)d_out;

    dim3 gemmGrid(Dq / 64, Mrows / 64);         // (8, 128)
    gemm64<<<gemmGrid, 256>>>(q, Wq, bq, nullptr, 0);
    gemm64<<<gemmGrid, 256>>>(k, Wk, bk, nullptr, 1);
    gemm64<<<gemmGrid, 256>>>(v, Wv, bv, nullptr, 2);

    dim3 attnGrid(Lq / 64, BHq);                // (64, 16)
    attn64<<<attnGrid, 64>>>();

    gemm64<<<gemmGrid, 256>>>(nullptr, Wo, bo, out, 3);
}

// round 2
// speedup vs baseline: 4.0133x; 4.0133x over previous
#include <cuda_runtime.h>
#include <math.h>

#define Bq   2
#define Lq   4096
#define Dq   512
#define Hq   8
#define DKq  64
#define BHq  (Bq*Hq)
#define Mrows (Bq*Lq)          // 8192

// ---------------- scratch (device globals; no allocations allowed) ----------
__device__ float g_Q[BHq * Lq * DKq];     // [b*H+h][l][dk]
__device__ float g_K[BHq * Lq * DKq];
__device__ float g_V[BHq * Lq * DKq];
__device__ float g_ctx[Mrows * Dq];       // [b*L + l][D]

// ---------------- tf32 helpers ----------------------------------------------
__device__ __forceinline__ unsigned f2tf(float f) {
    unsigned u;
    asm("cvt.rna.tf32.f32 %0, %1;" : "=r"(u) : "f"(f));
    return u;
}

// D(16x8) += A(16x8,row) * B(8x8,col)   [tf32 in, f32 accum]
__device__ __forceinline__ void mma8(float* c, const unsigned* a, const unsigned* b) {
    asm volatile(
        "mma.sync.aligned.m16n8k8.row.col.f32.tf32.tf32.f32 "
        "{%0,%1,%2,%3},{%4,%5,%6,%7},{%8,%9},{%0,%1,%2,%3};"
        : "+f"(c[0]), "+f"(c[1]), "+f"(c[2]), "+f"(c[3])
        : "r"(a[0]), "r"(a[1]), "r"(a[2]), "r"(a[3]),
          "r"(b[0]), "r"(b[1]));
}

// ---------------- tf32 tensor-core GEMM: out = x @ W + bias -----------------
// block tile 128x64, 8 warps (4x2), warp tile 32x32, BK=32
// mode 0/1/2 : write head-split into g_Q/g_K/g_V ; mode 3 : x:=g_ctx, plain out
__global__ __launch_bounds__(256) void gemm_tf32(const float* __restrict__ x,
                                                 const float* __restrict__ W,
                                                 const float* __restrict__ bias,
                                                 float* __restrict__ out_plain,
                                                 int mode)
{
    __shared__ unsigned As[128][36];
    __shared__ unsigned Bs[32][68];

    const float* xx = (mode == 3) ? g_ctx : x;
    float* out_hs = (mode == 0) ? g_Q : (mode == 1) ? g_K : g_V;

    const int m0 = blockIdx.y * 128;
    const int n0 = blockIdx.x * 64;
    const int tid = threadIdx.x;
    const int w = tid >> 5, lane = tid & 31;
    const int g = lane >> 2, t4 = lane & 3;
    const int wm = (w >> 1) * 32;          // warp m offset in tile (0..96)
    const int wn = (w & 1) * 32;           // warp n offset in tile (0 or 32)

    float acc[2][4][4];
    #pragma unroll
    for (int mt = 0; mt < 2; mt++)
        #pragma unroll
        for (int nt = 0; nt < 4; nt++)
            #pragma unroll
            for (int r = 0; r < 4; r++) acc[mt][nt][r] = 0.f;

    for (int k0 = 0; k0 < Dq; k0 += 32) {
        // load A tile 128x32
        #pragma unroll
        for (int l = 0; l < 4; l++) {
            int e = tid + l * 256;              // 0..1023 float4s
            int r = e >> 3, c4 = (e & 7) << 2;
            float4 v = *(const float4*)&xx[(size_t)(m0 + r) * Dq + k0 + c4];
            As[r][c4 + 0] = f2tf(v.x); As[r][c4 + 1] = f2tf(v.y);
            As[r][c4 + 2] = f2tf(v.z); As[r][c4 + 3] = f2tf(v.w);
        }
        // load B tile 32x64
        #pragma unroll
        for (int l = 0; l < 2; l++) {
            int e = tid + l * 256;              // 0..511 float4s
            int r = e >> 4, c4 = (e & 15) << 2;
            float4 v = *(const float4*)&W[(size_t)(k0 + r) * Dq + n0 + c4];
            Bs[r][c4 + 0] = f2tf(v.x); Bs[r][c4 + 1] = f2tf(v.y);
            Bs[r][c4 + 2] = f2tf(v.z); Bs[r][c4 + 3] = f2tf(v.w);
        }
        __syncthreads();

        #pragma unroll
        for (int kk = 0; kk < 32; kk += 8) {
            unsigned a[2][4], b[4][2];
            #pragma unroll
            for (int mt = 0; mt < 2; mt++) {
                int mr = wm + mt * 16;
                a[mt][0] = As[mr + g][kk + t4];
                a[mt][1] = As[mr + g + 8][kk + t4];
                a[mt][2] = As[mr + g][kk + t4 + 4];
                a[mt][3] = As[mr + g + 8][kk + t4 + 4];
            }
            #pragma unroll
            for (int nt = 0; nt < 4; nt++) {
                b[nt][0] = Bs[kk + t4][wn + nt * 8 + g];
                b[nt][1] = Bs[kk + t4 + 4][wn + nt * 8 + g];
            }
            #pragma unroll
            for (int mt = 0; mt < 2; mt++)
                #pragma unroll
                for (int nt = 0; nt < 4; nt++)
                    mma8(acc[mt][nt], a[mt], b[nt]);
        }
        __syncthreads();
    }

    // epilogue
    #pragma unroll
    for (int mt = 0; mt < 2; mt++) {
        #pragma unroll
        for (int nt = 0; nt < 4; nt++) {
            #pragma unroll
            for (int rr = 0; rr < 4; rr++) {
                int m = m0 + wm + mt * 16 + g + ((rr >> 1) ? 8 : 0);
                int n = n0 + wn + nt * 8 + (t4 << 1) + (rr & 1);
                float val = acc[mt][nt][rr] + bias[n];
                if (mode < 3) {
                    int b = m >> 12, l = m & 4095, h = n >> 6, dk = n & 63;
                    out_hs[(((size_t)(b * Hq + h) * Lq + l) << 6) + dk] = val;
                } else {
                    out_plain[(size_t)m * Dq + n] = val;
                }
            }
        }
    }
}

// ---------------- causal flash attention, tf32 tensor cores ------------------
// grid (L/64, B*H), block 128 (4 warps); each warp owns 16 q rows.
__global__ __launch_bounds__(128) void attn_tf32(void)
{
    __shared__ unsigned KVs[64][68];   // K tile, then reused for V tile
    __shared__ unsigned Ps[64][68];    // exp(S) staging

    const int bh = blockIdx.y, qt = blockIdx.x;
    const int tid = threadIdx.x;
    const int w = tid >> 5, lane = tid & 31;
    const int g = lane >> 2, t4 = lane & 3;

    const float* Qb = g_Q + (size_t)bh * Lq * DKq;
    const float* Kb = g_K + (size_t)bh * Lq * DKq;
    const float* Vb = g_V + (size_t)bh * Lq * DKq;

    const int q0 = qt * 64 + w * 16;       // warp's first global q row

    // Q fragments (scaled), persistent in registers: 8 k-steps x 4 regs
    unsigned qa[8][4];
    #pragma unroll
    for (int kk = 0; kk < 8; kk++) {
        qa[kk][0] = f2tf(Qb[(size_t)(q0 + g) * 64 + kk * 8 + t4] * 0.125f);
        qa[kk][1] = f2tf(Qb[(size_t)(q0 + g + 8) * 64 + kk * 8 + t4] * 0.125f);
        qa[kk][2] = f2tf(Qb[(size_t)(q0 + g) * 64 + kk * 8 + t4 + 4] * 0.125f);
        qa[kk][3] = f2tf(Qb[(size_t)(q0 + g + 8) * 64 + kk * 8 + t4 + 4] * 0.125f);
    }

    float acc[8][4];
    #pragma unroll
    for (int nt = 0; nt < 8; nt++)
        #pragma unroll
        for (int r = 0; r < 4; r++) acc[nt][r] = 0.f;

    float mrun0 = -INFINITY, mrun1 = -INFINITY;
    float lp0 = 0.f, lp1 = 0.f;

    for (int kt = 0; kt <= qt; kt++) {
        // ---- load K tile 64x64 ----
        #pragma unroll
        for (int l = 0; l < 8; l++) {
            int e = tid + l * 128;             // 0..1023 float4s
            int r = e >> 4, c4 = (e & 15) << 2;
            float4 v = *(const float4*)&Kb[((size_t)(kt * 64 + r) << 6) + c4];
            KVs[r][c4 + 0] = f2tf(v.x); KVs[r][c4 + 1] = f2tf(v.y);
            KVs[r][c4 + 2] = f2tf(v.z); KVs[r][c4 + 3] = f2tf(v.w);
        }
        __syncthreads();

        // ---- S = Q @ K^T (16x64 per warp) ----
        float s[8][4];
        #pragma unroll
        for (int nt = 0; nt < 8; nt++)
            #pragma unroll
            for (int r = 0; r < 4; r++) s[nt][r] = 0.f;

        #pragma unroll
        for (int nt = 0; nt < 8; nt++) {
            #pragma unroll
            for (int kk = 0; kk < 8; kk++) {
                unsigned b[2];
                b[0] = KVs[nt * 8 + g][kk * 8 + t4];
                b[1] = KVs[nt * 8 + g][kk * 8 + t4 + 4];
                mma8(s[nt], qa[kk], b);
            }
        }

        // ---- causal mask (diagonal tile only) ----
        if (kt == qt) {
            #pragma unroll
            for (int nt = 0; nt < 8; nt++) {
                int j = kt * 64 + nt * 8 + (t4 << 1);
                int r0 = q0 + g, r1 = q0 + g + 8;
                if (j     > r0) s[nt][0] = -INFINITY;
                if (j + 1 > r0) s[nt][1] = -INFINITY;
                if (j     > r1) s[nt][2] = -INFINITY;
                if (j + 1 > r1) s[nt][3] = -INFINITY;
            }
        }

        // ---- row max (2 rows per thread, reduce across quad) ----
        float tmax0 = -INFINITY, tmax1 = -INFINITY;
        #pragma unroll
        for (int nt = 0; nt < 8; nt++) {
            tmax0 = fmaxf(tmax0, fmaxf(s[nt][0], s[nt][1]));
            tmax1 = fmaxf(tmax1, fmaxf(s[nt][2], s[nt][3]));
        }
        tmax0 = fmaxf(tmax0, __shfl_xor_sync(0xffffffffu, tmax0, 1));
        tmax0 = fmaxf(tmax0, __shfl_xor_sync(0xffffffffu, tmax0, 2));
        tmax1 = fmaxf(tmax1, __shfl_xor_sync(0xffffffffu, tmax1, 1));
        tmax1 = fmaxf(tmax1, __shfl_xor_sync(0xffffffffu, tmax1, 2));

        float mn0 = fmaxf(mrun0, tmax0);
        float mn1 = fmaxf(mrun1, tmax1);
        float corr0 = __expf(mrun0 - mn0);
        float corr1 = __expf(mrun1 - mn1);
        #pragma unroll
        for (int nt = 0; nt < 8; nt++) {
            acc[nt][0] *= corr0; acc[nt][1] *= corr0;
            acc[nt][2] *= corr1; acc[nt][3] *= corr1;
        }
        lp0 *= corr0; lp1 *= corr1;

        // ---- exp + stage P to shared ----
        const int pr0 = w * 16 + g, pr1 = pr0 + 8;
        #pragma unroll
        for (int nt = 0; nt < 8; nt++) {
            float p0 = __expf(s[nt][0] - mn0);
            float p1 = __expf(s[nt][1] - mn0);
            float p2 = __expf(s[nt][2] - mn1);
            float p3 = __expf(s[nt][3] - mn1);
            lp0 += p0 + p1; lp1 += p2 + p3;
            int pc = nt * 8 + (t4 << 1);
            Ps[pr0][pc] = f2tf(p0); Ps[pr0][pc + 1] = f2tf(p1);
            Ps[pr1][pc] = f2tf(p2); Ps[pr1][pc + 1] = f2tf(p3);
        }
        mrun0 = mn0; mrun1 = mn1;

        __syncthreads();   // all warps done reading K before overwrite with V

        // ---- load V tile into the same buffer ----
        #pragma unroll
        for (int l = 0; l < 8; l++) {
            int e = tid + l * 128;
            int r = e >> 4, c4 = (e & 15) << 2;
            float4 v = *(const float4*)&Vb[((size_t)(kt * 64 + r) << 6) + c4];
            KVs[r][c4 + 0] = f2tf(v.x); KVs[r][c4 + 1] = f2tf(v.y);
            KVs[r][c4 + 2] = f2tf(v.z); KVs[r][c4 + 3] = f2tf(v.w);
        }
        __syncthreads();

        // ---- acc += P @ V ----
        #pragma unroll
        for (int kk = 0; kk < 8; kk++) {
            unsigned pa[4];
            pa[0] = Ps[pr0][kk * 8 + t4];
            pa[1] = Ps[pr1][kk * 8 + t4];
            pa[2] = Ps[pr0][kk * 8 + t4 + 4];
            pa[3] = Ps[pr1][kk * 8 + t4 + 4];
            #pragma unroll
            for (int nt = 0; nt < 8; nt++) {
                unsigned b[2];
                b[0] = KVs[kk * 8 + t4][nt * 8 + g];
                b[1] = KVs[kk * 8 + t4 + 4][nt * 8 + g];
                mma8(acc[nt], pa, b);
            }
        }
        __syncthreads();   // done with V before next iter's K load
    }

    // ---- epilogue: normalize, write ctx ----
    lp0 += __shfl_xor_sync(0xffffffffu, lp0, 1);
    lp0 += __shfl_xor_sync(0xffffffffu, lp0, 2);
    lp1 += __shfl_xor_sync(0xffffffffu, lp1, 1);
    lp1 += __shfl_xor_sync(0xffffffffu, lp1, 2);
    float inv0 = 1.f / lp0, inv1 = 1.f / lp1;

    const int b = bh >> 3, h = bh & 7;
    const int r0 = q0 + g, r1 = q0 + g + 8;
    #pragma unroll
    for (int nt = 0; nt < 8; nt++) {
        int col = h * 64 + nt * 8 + (t4 << 1);
        float2 o0, o1;
        o0.x = acc[nt][0] * inv0; o0.y = acc[nt][1] * inv0;
        o1.x = acc[nt][2] * inv1; o1.y = acc[nt][3] * inv1;
        *(float2*)&g_ctx[((size_t)(b * Lq) + r0) * Dq + col] = o0;
        *(float2*)&g_ctx[((size_t)(b * Lq) + r1) * Dq + col] = o1;
    }
}

// ---------------- launch ----------------------------------------------------
extern "C" void kernel_launch(void* const* d_in, const int* in_sizes, int n_in,
                              void* d_out, int out_size)
{
    const float* q  = (const float*)d_in[0];
    const float* k  = (const float*)d_in[1];
    const float* v  = (const float*)d_in[2];
    // d_in[3] = mask (int32 tril) — causality handled analytically
    const float* Wq = (const float*)d_in[4];
    const float* bq = (const float*)d_in[5];
    const float* Wk = (const float*)d_in[6];
    const float* bk = (const float*)d_in[7];
    const float* Wv = (const float*)d_in[8];
    const float* bv = (const float*)d_in[9];
    const float* Wo = (const float*)d_in[10];
    const float* bo = (const float*)d_in[11];
    float* out = (float*)d_out;

    dim3 gemmGrid(Dq / 64, Mrows / 128);        // (8, 64)
    gemm_tf32<<<gemmGrid, 256>>>(q, Wq, bq, nullptr, 0);
    gemm_tf32<<<gemmGrid, 256>>>(k, Wk, bk, nullptr, 1);
    gemm_tf32<<<gemmGrid, 256>>>(v, Wv, bv, nullptr, 2);

    dim3 attnGrid(Lq / 64, BHq);                // (64, 16)
    attn_tf32<<<attnGrid, 128>>>();

    gemm_tf32<<<gemmGrid, 256>>>(nullptr, Wo, bo, out, 3);
}

// round 3
// speedup vs baseline: 4.6148x; 1.1499x over previous
#include <cuda_runtime.h>
#include <math.h>

#define Bq   2
#define Lq   4096
#define Dq   512
#define Hq   8
#define DKq  64
#define BHq  (Bq*Hq)
#define Mrows (Bq*Lq)          // 8192

// pair-permute within each 8-block: (t4, t4+4) become adjacent
__host__ __device__ __forceinline__ int PC(int c) {
    return (c & ~7) | ((c & 3) << 1) | ((c >> 2) & 1);
}

// ---------------- scratch (device globals; no allocations allowed) ----------
// all pre-converted tf32 bits, pair-permuted
__device__ unsigned g_Q [BHq * Lq * DKq];   // [bh][l][pc(dk)], pre-scaled by 0.125
__device__ unsigned g_K [BHq * Lq * DKq];   // [bh][l][pc(dk)]
__device__ unsigned g_Vt[BHq * DKq * Lq];   // [bh][dk][pj(l)]  (transposed)
__device__ float    g_ctx[Mrows * Dq];      // [b*L + l][D]

// ---------------- tf32 helpers ----------------------------------------------
__device__ __forceinline__ unsigned f2tf(float f) {
    unsigned u;
    asm("cvt.rna.tf32.f32 %0, %1;" : "=r"(u) : "f"(f));
    return u;
}

__device__ __forceinline__ void mma8(float* c, const unsigned* a, const unsigned* b) {
    asm volatile(
        "mma.sync.aligned.m16n8k8.row.col.f32.tf32.tf32.f32 "
        "{%0,%1,%2,%3},{%4,%5,%6,%7},{%8,%9},{%0,%1,%2,%3};"
        : "+f"(c[0]), "+f"(c[1]), "+f"(c[2]), "+f"(c[3])
        : "r"(a[0]), "r"(a[1]), "r"(a[2]), "r"(a[3]),
          "r"(b[0]), "r"(b[1]));
}

// ---------------- tf32 tensor-core GEMM: out = x @ W + bias -----------------
// block tile 128x64, 8 warps (4x2), warp tile 32x32, BK=32, reg-prefetch pipe
// mode 0/1/2 : write permuted tf32 bits into g_Q/g_K/g_Vt ; mode 3 : ctx->out
__global__ __launch_bounds__(256) void gemm_tf32(
    const float* __restrict__ x0, const float* __restrict__ x1,
    const float* __restrict__ x2,
    const float* __restrict__ W0, const float* __restrict__ W1,
    const float* __restrict__ W2,
    const float* __restrict__ B0, const float* __restrict__ B1,
    const float* __restrict__ B2,
    float* __restrict__ out_plain, int mode_base)
{
    __shared__ unsigned As[128][36];
    __shared__ unsigned Bs[32][68];

    const int mode = mode_base + blockIdx.z;
    const float* xx   = (mode == 0) ? x0 : (mode == 1) ? x1 : (mode == 2) ? x2 : g_ctx;
    const float* W    = (blockIdx.z == 0) ? W0 : (blockIdx.z == 1) ? W1 : W2;
    const float* bias = (blockIdx.z == 0) ? B0 : (blockIdx.z == 1) ? B1 : B2;

    const int m0 = blockIdx.y * 128;
    const int n0 = blockIdx.x * 64;
    const int tid = threadIdx.x;
    const int w = tid >> 5, lane = tid & 31;
    const int g = lane >> 2, t4 = lane & 3;
    const int wm = (w >> 1) * 32;
    const int wn = (w & 1) * 32;

    float acc[2][4][4];
    #pragma unroll
    for (int mt = 0; mt < 2; mt++)
        #pragma unroll
        for (int nt = 0; nt < 4; nt++)
            #pragma unroll
            for (int r = 0; r < 4; r++) acc[mt][nt][r] = 0.f;

    float4 ra[4], rb[2];

#define LOAD_AB(K0)                                                        \
    {                                                                      \
        _Pragma("unroll")                                                  \
        for (int l = 0; l < 4; l++) {                                      \
            int e = tid + l * 256; int r = e >> 3, c4 = (e & 7) << 2;      \
            ra[l] = *(const float4*)&xx[(size_t)(m0 + r) * Dq + (K0) + c4];\
        }                                                                  \
        _Pragma("unroll")                                                  \
        for (int l = 0; l < 2; l++) {                                      \
            int e = tid + l * 256; int r = e >> 4, c4 = (e & 15) << 2;     \
            rb[l] = *(const float4*)&W[(size_t)((K0) + r) * Dq + n0 + c4]; \
        }                                                                  \
    }

    LOAD_AB(0);

    for (int k0 = 0; k0 < Dq; k0 += 32) {
        // store prefetched tiles (with cvt)
        #pragma unroll
        for (int l = 0; l < 4; l++) {
            int e = tid + l * 256; int r = e >> 3, c4 = (e & 7) << 2;
            As[r][c4 + 0] = f2tf(ra[l].x); As[r][c4 + 1] = f2tf(ra[l].y);
            As[r][c4 + 2] = f2tf(ra[l].z); As[r][c4 + 3] = f2tf(ra[l].w);
        }
        #pragma unroll
        for (int l = 0; l < 2; l++) {
            int e = tid + l * 256; int r = e >> 4, c4 = (e & 15) << 2;
            Bs[r][c4 + 0] = f2tf(rb[l].x); Bs[r][c4 + 1] = f2tf(rb[l].y);
            Bs[r][c4 + 2] = f2tf(rb[l].z); Bs[r][c4 + 3] = f2tf(rb[l].w);
        }
        __syncthreads();

        if (k0 + 32 < Dq) LOAD_AB(k0 + 32);

        #pragma unroll
        for (int kk = 0; kk < 32; kk += 8) {
            unsigned a[2][4], b[4][2];
            #pragma unroll
            for (int mt = 0; mt < 2; mt++) {
                int mr = wm + mt * 16;
                a[mt][0] = As[mr + g][kk + t4];
                a[mt][1] = As[mr + g + 8][kk + t4];
                a[mt][2] = As[mr + g][kk + t4 + 4];
                a[mt][3] = As[mr + g + 8][kk + t4 + 4];
            }
            #pragma unroll
            for (int nt = 0; nt < 4; nt++) {
                b[nt][0] = Bs[kk + t4][wn + nt * 8 + g];
                b[nt][1] = Bs[kk + t4 + 4][wn + nt * 8 + g];
            }
            #pragma unroll
            for (int mt = 0; mt < 2; mt++)
                #pragma unroll
                for (int nt = 0; nt < 4; nt++)
                    mma8(acc[mt][nt], a[mt], b[nt]);
        }
        __syncthreads();
    }
#undef LOAD_AB

    // epilogue
    #pragma unroll
    for (int mt = 0; mt < 2; mt++) {
        #pragma unroll
        for (int nt = 0; nt < 4; nt++) {
            #pragma unroll
            for (int rr = 0; rr < 4; rr++) {
                int m = m0 + wm + mt * 16 + g + ((rr >> 1) ? 8 : 0);
                int n = n0 + wn + nt * 8 + (t4 << 1) + (rr & 1);
                float val = acc[mt][nt][rr] + bias[n];
                if (mode == 3) {
                    out_plain[(size_t)m * Dq + n] = val;
                } else {
                    int bb = m >> 12, l = m & 4095, h = n >> 6, dk = n & 63;
                    size_t bh = (size_t)(bb * Hq + h);
                    if (mode == 0)
                        g_Q[(bh * Lq + l) * 64 + PC(dk)] = f2tf(val * 0.125f);
                    else if (mode == 1)
                        g_K[(bh * Lq + l) * 64 + PC(dk)] = f2tf(val);
                    else
                        g_Vt[(bh * 64 + dk) * Lq + PC(l & 4095)] = f2tf(val);
                }
            }
        }
    }
}

// ---------------- attention helpers ------------------------------------------
__device__ __forceinline__ void softmax_update(
    float s[8][4], float acc[8][4], float& m0, float& m1, float& l0, float& l1,
    bool diag, int r0, int r1, int jbase, int t4)
{
    if (diag) {
        #pragma unroll
        for (int nt = 0; nt < 8; nt++) {
            int j = jbase + nt * 8 + (t4 << 1);
            if (j     > r0) s[nt][0] = -INFINITY;
            if (j + 1 > r0) s[nt][1] = -INFINITY;
            if (j     > r1) s[nt][2] = -INFINITY;
            if (j + 1 > r1) s[nt][3] = -INFINITY;
        }
    }
    float t0 = -INFINITY, t1 = -INFINITY;
    #pragma unroll
    for (int nt = 0; nt < 8; nt++) {
        t0 = fmaxf(t0, fmaxf(s[nt][0], s[nt][1]));
        t1 = fmaxf(t1, fmaxf(s[nt][2], s[nt][3]));
    }
    t0 = fmaxf(t0, __shfl_xor_sync(0xffffffffu, t0, 1));
    t0 = fmaxf(t0, __shfl_xor_sync(0xffffffffu, t0, 2));
    t1 = fmaxf(t1, __shfl_xor_sync(0xffffffffu, t1, 1));
    t1 = fmaxf(t1, __shfl_xor_sync(0xffffffffu, t1, 2));

    float mn0 = fmaxf(m0, t0), mn1 = fmaxf(m1, t1);
    float c0 = __expf(m0 - mn0), c1 = __expf(m1 - mn1);
    #pragma unroll
    for (int nt = 0; nt < 8; nt++) {
        acc[nt][0] *= c0; acc[nt][1] *= c0;
        acc[nt][2] *= c1; acc[nt][3] *= c1;
    }
    l0 *= c0; l1 *= c1;
    #pragma unroll
    for (int nt = 0; nt < 8; nt++) {
        float p0 = __expf(s[nt][0] - mn0);
        float p1 = __expf(s[nt][1] - mn0);
        float p2 = __expf(s[nt][2] - mn1);
        float p3 = __expf(s[nt][3] - mn1);
        s[nt][0] = p0; s[nt][1] = p1; s[nt][2] = p2; s[nt][3] = p3;
        l0 += p0 + p1; l1 += p2 + p3;
    }
    m0 = mn0; m1 = mn1;
}

// convert softmax C-fragment rows into A-fragment via intra-quad shuffles
__device__ __forceinline__ void make_pa(unsigned pa[4], const float s4[4],
                                        int src0, int e)
{
    float v00 = __shfl_sync(0xffffffffu, s4[0], src0);
    float v01 = __shfl_sync(0xffffffffu, s4[1], src0);
    float v20 = __shfl_sync(0xffffffffu, s4[0], src0 + 2);
    float v21 = __shfl_sync(0xffffffffu, s4[1], src0 + 2);
    float v10 = __shfl_sync(0xffffffffu, s4[2], src0);
    float v11 = __shfl_sync(0xffffffffu, s4[3], src0);
    float v30 = __shfl_sync(0xffffffffu, s4[2], src0 + 2);
    float v31 = __shfl_sync(0xffffffffu, s4[3], src0 + 2);
    pa[0] = f2tf(e ? v01 : v00);
    pa[1] = f2tf(e ? v11 : v10);
    pa[2] = f2tf(e ? v21 : v20);
    pa[3] = f2tf(e ? v31 : v30);
}

// ---------------- causal flash attention, dual balanced q-tiles --------------
// block: 128 thr (4 warps). q-tiles tA = p, tB = 63-p -> uniform 65 tiles work
__global__ __launch_bounds__(128) void attn_tf32(void)
{
    __shared__ unsigned Ks[64][72];
    __shared__ unsigned VT[64][72];

    const int p = blockIdx.x, bh = blockIdx.y;
    const int tA = p, tB = 63 - p;
    const int tid = threadIdx.x;
    const int w = tid >> 5, lane = tid & 31;
    const int g = lane >> 2, t4 = lane & 3;
    const int src0 = (lane & ~3) | (t4 >> 1);
    const int e = t4 & 1;

    const unsigned* Qb = g_Q + (size_t)bh * Lq * 64;
    const unsigned* Kb = g_K + (size_t)bh * Lq * 64;
    const unsigned* Vb = g_Vt + (size_t)bh * 64 * Lq;

    const int rA0 = tA * 64 + w * 16 + g, rA1 = rA0 + 8;
    const int rB0 = tB * 64 + w * 16 + g, rB1 = rB0 + 8;

    float accA[8][4], accB[8][4];
    #pragma unroll
    for (int nt = 0; nt < 8; nt++)
        #pragma unroll
        for (int r = 0; r < 4; r++) { accA[nt][r] = 0.f; accB[nt][r] = 0.f; }
    float mA0 = -INFINITY, mA1 = -INFINITY, lA0 = 0.f, lA1 = 0.f;
    float mB0 = -INFINITY, mB1 = -INFINITY, lB0 = 0.f, lB1 = 0.f;

    for (int kt = 0; kt <= tB; kt++) {
        const bool actA = (kt <= tA);

        // ---- fill K (rows=j, paired dk) and V^T (rows=dk, paired j) ----
        #pragma unroll
        for (int l2 = 0; l2 < 8; l2++) {
            int ee = tid + l2 * 128;
            int r = ee >> 4, c4 = (ee & 15) << 2;
            *(uint4*)&Ks[r][c4] = *(const uint4*)&Kb[((size_t)(kt * 64 + r)) * 64 + c4];
            *(uint4*)&VT[r][c4] = *(const uint4*)&Vb[(size_t)r * Lq + kt * 64 + c4];
        }
        __syncthreads();

        // ---- S = Q @ K^T for both tiles (B-fragments shared) ----
        float sA[8][4], sB[8][4];
        #pragma unroll
        for (int nt = 0; nt < 8; nt++)
            #pragma unroll
            for (int r = 0; r < 4; r++) { sA[nt][r] = 0.f; sB[nt][r] = 0.f; }

        #pragma unroll
        for (int kk = 0; kk < 8; kk++) {
            uint2 qlo = *(const uint2*)&Qb[(size_t)rB0 * 64 + kk * 8 + 2 * t4];
            uint2 qhi = *(const uint2*)&Qb[(size_t)rB1 * 64 + kk * 8 + 2 * t4];
            unsigned qB[4] = {qlo.x, qhi.x, qlo.y, qhi.y};
            unsigned qA[4];
            if (actA) {
                uint2 alo = *(const uint2*)&Qb[(size_t)rA0 * 64 + kk * 8 + 2 * t4];
                uint2 ahi = *(const uint2*)&Qb[(size_t)rA1 * 64 + kk * 8 + 2 * t4];
                qA[0] = alo.x; qA[1] = ahi.x; qA[2] = alo.y; qA[3] = ahi.y;
            }
            #pragma unroll
            for (int nt = 0; nt < 8; nt++) {
                uint2 bb = *(const uint2*)&Ks[nt * 8 + g][kk * 8 + 2 * t4];
                unsigned b2[2] = {bb.x, bb.y};
                mma8(sB[nt], qB, b2);
                if (actA) mma8(sA[nt], qA, b2);
            }
        }

        // ---- softmax updates ----
        softmax_update(sB, accB, mB0, mB1, lB0, lB1, kt == tB, rB0, rB1, kt * 64, t4);
        if (actA)
            softmax_update(sA, accA, mA0, mA1, lA0, lA1, kt == tA, rA0, rA1, kt * 64, t4);

        // ---- acc += P @ V (V-fragments shared) ----
        #pragma unroll
        for (int kk = 0; kk < 8; kk++) {
            unsigned paB[4], paA[4];
            make_pa(paB, sB[kk], src0, e);
            if (actA) make_pa(paA, sA[kk], src0, e);
            #pragma unroll
            for (int nt = 0; nt < 8; nt++) {
                uint2 bb = *(const uint2*)&VT[nt * 8 + g][kk * 8 + 2 * t4];
                unsigned b2[2] = {bb.x, bb.y};
                mma8(accB[nt], paB, b2);
                if (actA) mma8(accA[nt], paA, b2);
            }
        }
        __syncthreads();
    }

    // ---- epilogue ----
    lA0 += __shfl_xor_sync(0xffffffffu, lA0, 1);
    lA0 += __shfl_xor_sync(0xffffffffu, lA0, 2);
    lA1 += __shfl_xor_sync(0xffffffffu, lA1, 1);
    lA1 += __shfl_xor_sync(0xffffffffu, lA1, 2);
    lB0 += __shfl_xor_sync(0xffffffffu, lB0, 1);
    lB0 += __shfl_xor_sync(0xffffffffu, lB0, 2);
    lB1 += __shfl_xor_sync(0xffffffffu, lB1, 1);
    lB1 += __shfl_xor_sync(0xffffffffu, lB1, 2);
    const float iA0 = 1.f / lA0, iA1 = 1.f / lA1;
    const float iB0 = 1.f / lB0, iB1 = 1.f / lB1;

    const int b = bh >> 3, h = bh & 7;
    #pragma unroll
    for (int nt = 0; nt < 8; nt++) {
        int col = h * 64 + nt * 8 + (t4 << 1);
        float2 o;
        o.x = accA[nt][0] * iA0; o.y = accA[nt][1] * iA0;
        *(float2*)&g_ctx[((size_t)(b * Lq) + rA0) * Dq + col] = o;
        o.x = accA[nt][2] * iA1; o.y = accA[nt][3] * iA1;
        *(float2*)&g_ctx[((size_t)(b * Lq) + rA1) * Dq + col] = o;
        o.x = accB[nt][0] * iB0; o.y = accB[nt][1] * iB0;
        *(float2*)&g_ctx[((size_t)(b * Lq) + rB0) * Dq + col] = o;
        o.x = accB[nt][2] * iB1; o.y = accB[nt][3] * iB1;
        *(float2*)&g_ctx[((size_t)(b * Lq) + rB1) * Dq + col] = o;
    }
}

// ---------------- launch ----------------------------------------------------
extern "C" void kernel_launch(void* const* d_in, const int* in_sizes, int n_in,
                              void* d_out, int out_size)
{
    const float* q  = (const float*)d_in[0];
    const float* k  = (const float*)d_in[1];
    const float* v  = (const float*)d_in[2];
    // d_in[3] = mask (int32 tril) — causality handled analytically
    const float* Wq = (const float*)d_in[4];
    const float* bq = (const float*)d_in[5];
    const float* Wk = (const float*)d_in[6];
    const float* bk = (const float*)d_in[7];
    const float* Wv = (const float*)d_in[8];
    const float* bv = (const float*)d_in[9];
    const float* Wo = (const float*)d_in[10];
    const float* bo = (const float*)d_in[11];
    float* out = (float*)d_out;

    // merged Q/K/V projections (one tail instead of three)
    gemm_tf32<<<dim3(Dq / 64, Mrows / 128, 3), 256>>>(
        q, k, v, Wq, Wk, Wv, bq, bk, bv, nullptr, 0);

    attn_tf32<<<dim3(32, BHq), 128>>>();

    gemm_tf32<<<dim3(Dq / 64, Mrows / 128, 1), 256>>>(
        nullptr, nullptr, nullptr, Wo, Wo, Wo, bo, bo, bo, out, 3);
}

// round 4
// speedup vs baseline: 5.6723x; 1.2292x over previous
#include <cuda_runtime.h>
#include <math.h>

#define Bq   2
#define Lq   4096
#define Dq   512
#define Hq   8
#define DKq  64
#define BHq  (Bq*Hq)
#define Mrows (Bq*Lq)          // 8192

// pair-permute within each 8-block: (t4, t4+4) become adjacent
__host__ __device__ __forceinline__ int PC(int c) {
    return (c & ~7) | ((c & 3) << 1) | ((c >> 2) & 1);
}

// ---------------- scratch (device globals; no allocations allowed) ----------
__device__ unsigned g_Q [BHq * Lq * DKq];   // [bh][l][pc(dk)], pre-scaled 0.125
__device__ unsigned g_K [BHq * Lq * DKq];   // [bh][l][pc(dk)]
__device__ unsigned g_Vt[BHq * DKq * Lq];   // [bh][dk][pc(l)] (transposed)
__device__ float    g_ctx[Mrows * Dq];      // [b*L + l][D]

// ---------------- helpers -----------------------------------------------------
__device__ __forceinline__ unsigned f2tf(float f) {
    unsigned u;
    asm("cvt.rna.tf32.f32 %0, %1;" : "=r"(u) : "f"(f));
    return u;
}

__device__ __forceinline__ void mma8(float* c, const unsigned* a, const unsigned* b) {
    asm volatile(
        "mma.sync.aligned.m16n8k8.row.col.f32.tf32.tf32.f32 "
        "{%0,%1,%2,%3},{%4,%5,%6,%7},{%8,%9},{%0,%1,%2,%3};"
        : "+f"(c[0]), "+f"(c[1]), "+f"(c[2]), "+f"(c[3])
        : "r"(a[0]), "r"(a[1]), "r"(a[2]), "r"(a[3]),
          "r"(b[0]), "r"(b[1]));
}

__device__ __forceinline__ void cpa16(unsigned s, const void* g) {
    asm volatile("cp.async.cg.shared.global [%0], [%1], 16;" :: "r"(s), "l"(g));
}
#define CP_COMMIT asm volatile("cp.async.commit_group;")
#define CP_WAIT0  asm volatile("cp.async.wait_group 0;")

// ---------------- tf32 GEMM: out = x @ W + bias --------------------------------
// block 128x64, 4 warps (2x2) of 64x32 warp tiles, BK=32, 128 threads
// mode 0/1/2 : write permuted tf32 into g_Q/g_K/g_Vt ; mode 3 : ctx -> out
__global__ __launch_bounds__(128) void gemm_tf32(
    const float* __restrict__ x0, const float* __restrict__ x1,
    const float* __restrict__ x2,
    const float* __restrict__ W0, const float* __restrict__ W1,
    const float* __restrict__ W2,
    const float* __restrict__ B0, const float* __restrict__ B1,
    const float* __restrict__ B2,
    float* __restrict__ out_plain, int mode_base)
{
    __shared__ unsigned As[128][36];   // pc'd k columns
    __shared__ unsigned Bs[32][68];

    const int mode = mode_base + blockIdx.z;
    const float* xx   = (mode == 0) ? x0 : (mode == 1) ? x1 : (mode == 2) ? x2 : g_ctx;
    const float* W    = (blockIdx.z == 0) ? W0 : (blockIdx.z == 1) ? W1 : W2;
    const float* bias = (blockIdx.z == 0) ? B0 : (blockIdx.z == 1) ? B1 : B2;

    const int m0 = blockIdx.y * 128;
    const int n0 = blockIdx.x * 64;
    const int tid = threadIdx.x;
    const int w = tid >> 5, lane = tid & 31;
    const int g = lane >> 2, t4 = lane & 3;
    const int wm = (w >> 1) * 64;          // 0 or 64
    const int wn = (w & 1) * 32;           // 0 or 32

    float acc[4][4][4];
    #pragma unroll
    for (int mt = 0; mt < 4; mt++)
        #pragma unroll
        for (int nt = 0; nt < 4; nt++)
            #pragma unroll
            for (int r = 0; r < 4; r++) acc[mt][nt][r] = 0.f;

    for (int k0 = 0; k0 < Dq; k0 += 32) {
        // A tile 128x32 -> As (pc'd cols)
        #pragma unroll
        for (int l = 0; l < 8; l++) {
            int e = tid + l * 128;
            int r = e >> 3, c4 = (e & 7) << 2;
            float4 v = *(const float4*)&xx[(size_t)(m0 + r) * Dq + k0 + c4];
            As[r][PC(c4 + 0)] = f2tf(v.x);
            As[r][PC(c4 + 1)] = f2tf(v.y);
            As[r][PC(c4 + 2)] = f2tf(v.z);
            As[r][PC(c4 + 3)] = f2tf(v.w);
        }
        // B tile 32x64
        #pragma unroll
        for (int l = 0; l < 4; l++) {
            int e = tid + l * 128;
            int r = e >> 4, c4 = (e & 15) << 2;
            float4 v = *(const float4*)&W[(size_t)(k0 + r) * Dq + n0 + c4];
            Bs[r][c4 + 0] = f2tf(v.x); Bs[r][c4 + 1] = f2tf(v.y);
            Bs[r][c4 + 2] = f2tf(v.z); Bs[r][c4 + 3] = f2tf(v.w);
        }
        __syncthreads();

        #pragma unroll
        for (int kk = 0; kk < 32; kk += 8) {
            unsigned a[4][4], b[4][2];
            #pragma unroll
            for (int mt = 0; mt < 4; mt++) {
                int mr = wm + mt * 16;
                uint2 lo = *(const uint2*)&As[mr + g][kk + 2 * t4];
                uint2 hi = *(const uint2*)&As[mr + g + 8][kk + 2 * t4];
                a[mt][0] = lo.x; a[mt][1] = hi.x; a[mt][2] = lo.y; a[mt][3] = hi.y;
            }
            #pragma unroll
            for (int nt = 0; nt < 4; nt++) {
                b[nt][0] = Bs[kk + t4][wn + nt * 8 + g];
                b[nt][1] = Bs[kk + t4 + 4][wn + nt * 8 + g];
            }
            #pragma unroll
            for (int mt = 0; mt < 4; mt++)
                #pragma unroll
                for (int nt = 0; nt < 4; nt++)
                    mma8(acc[mt][nt], a[mt], b[nt]);
        }
        __syncthreads();
    }

    // epilogue
    #pragma unroll
    for (int mt = 0; mt < 4; mt++) {
        #pragma unroll
        for (int nt = 0; nt < 4; nt++) {
            #pragma unroll
            for (int rr = 0; rr < 4; rr++) {
                int m = m0 + wm + mt * 16 + g + ((rr >> 1) ? 8 : 0);
                int n = n0 + wn + nt * 8 + (t4 << 1) + (rr & 1);
                float val = acc[mt][nt][rr] + bias[n];
                if (mode == 3) {
                    out_plain[(size_t)m * Dq + n] = val;
                } else {
                    int bb = m >> 12, l = m & 4095, h = n >> 6, dk = n & 63;
                    size_t bh = (size_t)(bb * Hq + h);
                    if (mode == 0)
                        g_Q[(bh * Lq + l) * 64 + PC(dk)] = f2tf(val * 0.125f);
                    else if (mode == 1)
                        g_K[(bh * Lq + l) * 64 + PC(dk)] = f2tf(val);
                    else
                        g_Vt[(bh * 64 + dk) * Lq + (l & ~7) + PC(l & 7)] = f2tf(val);
                }
            }
        }
    }
}

// ---------------- attention helpers --------------------------------------------
__device__ __forceinline__ void softmax_update(
    float s[8][4], float acc[8][4], float& m0, float& m1, float& l0, float& l1,
    bool diag, int r0, int r1, int jbase, int t4)
{
    if (diag) {
        #pragma unroll
        for (int nt = 0; nt < 8; nt++) {
            int j = jbase + nt * 8 + (t4 << 1);
            if (j     > r0) s[nt][0] = -INFINITY;
            if (j + 1 > r0) s[nt][1] = -INFINITY;
            if (j     > r1) s[nt][2] = -INFINITY;
            if (j + 1 > r1) s[nt][3] = -INFINITY;
        }
    }
    float t0 = -INFINITY, t1 = -INFINITY;
    #pragma unroll
    for (int nt = 0; nt < 8; nt++) {
        t0 = fmaxf(t0, fmaxf(s[nt][0], s[nt][1]));
        t1 = fmaxf(t1, fmaxf(s[nt][2], s[nt][3]));
    }
    t0 = fmaxf(t0, __shfl_xor_sync(0xffffffffu, t0, 1));
    t0 = fmaxf(t0, __shfl_xor_sync(0xffffffffu, t0, 2));
    t1 = fmaxf(t1, __shfl_xor_sync(0xffffffffu, t1, 1));
    t1 = fmaxf(t1, __shfl_xor_sync(0xffffffffu, t1, 2));

    float mn0 = fmaxf(m0, t0), mn1 = fmaxf(m1, t1);
    float c0 = __expf(m0 - mn0), c1 = __expf(m1 - mn1);
    #pragma unroll
    for (int nt = 0; nt < 8; nt++) {
        acc[nt][0] *= c0; acc[nt][1] *= c0;
        acc[nt][2] *= c1; acc[nt][3] *= c1;
    }
    l0 *= c0; l1 *= c1;
    #pragma unroll
    for (int nt = 0; nt < 8; nt++) {
        float p0 = __expf(s[nt][0] - mn0);
        float p1 = __expf(s[nt][1] - mn0);
        float p2 = __expf(s[nt][2] - mn1);
        float p3 = __expf(s[nt][3] - mn1);
        s[nt][0] = p0; s[nt][1] = p1; s[nt][2] = p2; s[nt][3] = p3;
        l0 += p0 + p1; l1 += p2 + p3;
    }
    m0 = mn0; m1 = mn1;
}

// softmax C-fragment rows -> next-MMA A-fragment, intra-quad shuffles
__device__ __forceinline__ void make_pa(unsigned pa[4], const float s4[4],
                                        int src0, int e)
{
    float v00 = __shfl_sync(0xffffffffu, s4[0], src0);
    float v01 = __shfl_sync(0xffffffffu, s4[1], src0);
    float v20 = __shfl_sync(0xffffffffu, s4[0], src0 + 2);
    float v21 = __shfl_sync(0xffffffffu, s4[1], src0 + 2);
    float v10 = __shfl_sync(0xffffffffu, s4[2], src0);
    float v11 = __shfl_sync(0xffffffffu, s4[3], src0);
    float v30 = __shfl_sync(0xffffffffu, s4[2], src0 + 2);
    float v31 = __shfl_sync(0xffffffffu, s4[3], src0 + 2);
    pa[0] = f2tf(e ? v01 : v00);
    pa[1] = f2tf(e ? v11 : v10);
    pa[2] = f2tf(e ? v21 : v20);
    pa[3] = f2tf(e ? v31 : v30);
}

// ---------------- causal flash attention ---------------------------------------
// 128 thr (4 warps), one 64-row q tile; qt = 63 - blockIdx.x (long blocks first);
// cp.async pipelines: V fill overlaps QK+softmax, next K fill overlaps PV.
__global__ __launch_bounds__(128) void attn_tf32(void)
{
    __shared__ unsigned Ks[64][72];
    __shared__ unsigned VT[64][72];

    const int qt = 63 - blockIdx.x;
    const int bh = blockIdx.y;
    const int tid = threadIdx.x;
    const int w = tid >> 5, lane = tid & 31;
    const int g = lane >> 2, t4 = lane & 3;
    const int src0 = (lane & ~3) | (t4 >> 1);
    const int e = t4 & 1;

    const unsigned* Qb = g_Q + (size_t)bh * Lq * 64;
    const unsigned* Kb = g_K + (size_t)bh * Lq * 64;
    const unsigned* Vb = g_Vt + (size_t)bh * 64 * Lq;

    const int r0 = qt * 64 + w * 16 + g, r1 = r0 + 8;

    // fill addressing (per-thread constants)
    const int fr = tid >> 3;               // 0..15  (row group base /4)
    const int fc = (tid & 7) << 4;         // not used; recompute per l

    // persistent Q fragments (pre-scaled, pre-permuted)
    unsigned qa[8][4];
    #pragma unroll
    for (int kk = 0; kk < 8; kk++) {
        uint2 lo = *(const uint2*)&Qb[(size_t)r0 * 64 + kk * 8 + 2 * t4];
        uint2 hi = *(const uint2*)&Qb[(size_t)r1 * 64 + kk * 8 + 2 * t4];
        qa[kk][0] = lo.x; qa[kk][1] = hi.x; qa[kk][2] = lo.y; qa[kk][3] = hi.y;
    }
    (void)fr; (void)fc;

    float acc[8][4];
    #pragma unroll
    for (int nt = 0; nt < 8; nt++)
        #pragma unroll
        for (int r = 0; r < 4; r++) acc[nt][r] = 0.f;
    float m0 = -INFINITY, m1 = -INFINITY, l0 = 0.f, l1 = 0.f;

    // prologue: fill K(0)
    #pragma unroll
    for (int l = 0; l < 8; l++) {
        int ee = tid + l * 128;
        int r = ee >> 4, c4 = (ee & 15) << 2;
        cpa16((unsigned)__cvta_generic_to_shared(&Ks[r][c4]),
              &Kb[((size_t)r) * 64 + c4]);
    }
    CP_COMMIT;
    CP_WAIT0;
    __syncthreads();

    for (int kt = 0; kt <= qt; kt++) {
        // issue V(kt) fill (overlaps QK + softmax)
        #pragma unroll
        for (int l = 0; l < 8; l++) {
            int ee = tid + l * 128;
            int r = ee >> 4, c4 = (ee & 15) << 2;
            cpa16((unsigned)__cvta_generic_to_shared(&VT[r][c4]),
                  &Vb[(size_t)r * Lq + kt * 64 + c4]);
        }
        CP_COMMIT;

        // ---- S = Q @ K^T ----
        float s[8][4];
        #pragma unroll
        for (int nt = 0; nt < 8; nt++)
            #pragma unroll
            for (int r = 0; r < 4; r++) s[nt][r] = 0.f;
        #pragma unroll
        for (int nt = 0; nt < 8; nt++) {
            #pragma unroll
            for (int kk = 0; kk < 8; kk++) {
                uint2 bb = *(const uint2*)&Ks[nt * 8 + g][kk * 8 + 2 * t4];
                unsigned b2[2] = {bb.x, bb.y};
                mma8(s[nt], qa[kk], b2);
            }
        }

        softmax_update(s, acc, m0, m1, l0, l1, kt == qt, r0, r1, kt * 64, t4);

        CP_WAIT0;
        __syncthreads();    // VT ready; all warps done reading Ks

        // issue K(kt+1) fill (overlaps PV)
        if (kt < qt) {
            #pragma unroll
            for (int l = 0; l < 8; l++) {
                int ee = tid + l * 128;
                int r = ee >> 4, c4 = (ee & 15) << 2;
                cpa16((unsigned)__cvta_generic_to_shared(&Ks[r][c4]),
                      &Kb[((size_t)((kt + 1) * 64 + r)) * 64 + c4]);
            }
            CP_COMMIT;
        }

        // ---- acc += P @ V ----
        #pragma unroll
        for (int kk = 0; kk < 8; kk++) {
            unsigned pa[4];
            make_pa(pa, s[kk], src0, e);
            #pragma unroll
            for (int nt = 0; nt < 8; nt++) {
                uint2 bb = *(const uint2*)&VT[nt * 8 + g][kk * 8 + 2 * t4];
                unsigned b2[2] = {bb.x, bb.y};
                mma8(acc[nt], pa, b2);
            }
        }

        CP_WAIT0;
        __syncthreads();    // Ks(kt+1) ready; all warps done reading VT
    }

    // ---- epilogue ----
    l0 += __shfl_xor_sync(0xffffffffu, l0, 1);
    l0 += __shfl_xor_sync(0xffffffffu, l0, 2);
    l1 += __shfl_xor_sync(0xffffffffu, l1, 1);
    l1 += __shfl_xor_sync(0xffffffffu, l1, 2);
    const float i0 = 1.f / l0, i1 = 1.f / l1;

    const int b = bh >> 3, h = bh & 7;
    #pragma unroll
    for (int nt = 0; nt < 8; nt++) {
        int col = h * 64 + nt * 8 + (t4 << 1);
        float2 o;
        o.x = acc[nt][0] * i0; o.y = acc[nt][1] * i0;
        *(float2*)&g_ctx[((size_t)(b * Lq) + r0) * Dq + col] = o;
        o.x = acc[nt][2] * i1; o.y = acc[nt][3] * i1;
        *(float2*)&g_ctx[((size_t)(b * Lq) + r1) * Dq + col] = o;
    }
}

// ---------------- launch --------------------------------------------------------
extern "C" void kernel_launch(void* const* d_in, const int* in_sizes, int n_in,
                              void* d_out, int out_size)
{
    const float* q  = (const float*)d_in[0];
    const float* k  = (const float*)d_in[1];
    const float* v  = (const float*)d_in[2];
    // d_in[3] = mask (int32 tril) — causality handled analytically
    const float* Wq = (const float*)d_in[4];
    const float* bq = (const float*)d_in[5];
    const float* Wk = (const float*)d_in[6];
    const float* bk = (const float*)d_in[7];
    const float* Wv = (const float*)d_in[8];
    const float* bv = (const float*)d_in[9];
    const float* Wo = (const float*)d_in[10];
    const float* bo = (const float*)d_in[11];
    float* out = (float*)d_out;

    gemm_tf32<<<dim3(Dq / 64, Mrows / 128, 3), 128>>>(
        q, k, v, Wq, Wk, Wv, bq, bk, bv, nullptr, 0);

    attn_tf32<<<dim3(64, BHq), 128>>>();

    gemm_tf32<<<dim3(Dq / 64, Mrows / 128, 1), 128>>>(
        nullptr, nullptr, nullptr, Wo, Wo, Wo, bo, bo, bo, out, 3);
}